// round 1
// baseline (speedup 1.0000x reference)
#include <cuda_runtime.h>

#define B_     64
#define IN_CH_ 16
#define H_     256
#define FDIM_  128
#define NF_    1001
#define G4_    1024      // 4*H
#define INS0_  144       // FDIM + IN_CH

// Scratch (allocation-free: device globals)
__device__ float g_fproj[NF_ * G4_];   // [t][4H]  batch-independent layer-0 input projection
__device__ float g_xproj[B_ * G4_];    // [b][4H]  x-part + layer-0 biases

__device__ __forceinline__ float fast_sigmoid(float x) {
    float e = __expf(-x);                       // EX2
    return __fdividef(1.0f, 1.0f + e);          // RCP (+mul)
}
__device__ __forceinline__ float fast_tanh(float x) {
    float e = __expf(-2.0f * x);                // EX2
    return __fdividef(2.0f, 1.0f + e) - 1.0f;   // RCP (+mul), (1-e)/(1+e)
}

// ---------------------------------------------------------------------------
// Precompute 1: F_proj[t, g] = sum_i f[t,i] * W_ih0[g, i]   (i < 128)
// grid (ceil(NF/16)=63, 4), block 256. Each block: 16 timesteps x 256 gates.
// ---------------------------------------------------------------------------
__global__ void fproj_kernel(const float* __restrict__ f,
                             const float* __restrict__ Wih0) {
    __shared__ float fs[16][FDIM_];
    const int tid = threadIdx.x;
    const int t0 = blockIdx.x * 16;

    for (int idx = tid; idx < 16 * FDIM_; idx += 256) {
        int tt = idx >> 7, ii = idx & 127;
        int t = t0 + tt;
        fs[tt][ii] = (t < NF_) ? f[t * FDIM_ + ii] : 0.0f;
    }
    __syncthreads();

    const int g = blockIdx.y * 256 + tid;
    float acc[16];
    #pragma unroll
    for (int tt = 0; tt < 16; ++tt) acc[tt] = 0.0f;

    #pragma unroll 4
    for (int i = 0; i < FDIM_; ++i) {
        float w = Wih0[g * INS0_ + i];
        #pragma unroll
        for (int tt = 0; tt < 16; ++tt) acc[tt] += w * fs[tt][i];
    }
    #pragma unroll
    for (int tt = 0; tt < 16; ++tt) {
        int t = t0 + tt;
        if (t < NF_) g_fproj[(size_t)t * G4_ + g] = acc[tt];
    }
}

// ---------------------------------------------------------------------------
// Precompute 2: X_proj[b, g] = b_ih0[g] + b_hh0[g] + sum_j x[b,j]*W_ih0[g,128+j]
// grid (64, 4), block 256.
// ---------------------------------------------------------------------------
__global__ void xproj_kernel(const float* __restrict__ x,
                             const float* __restrict__ Wih0,
                             const float* __restrict__ bih0,
                             const float* __restrict__ bhh0) {
    const int b = blockIdx.x;
    const int g = blockIdx.y * 256 + threadIdx.x;
    float acc = bih0[g] + bhh0[g];
    #pragma unroll
    for (int j = 0; j < IN_CH_; ++j)
        acc += x[b * IN_CH_ + j] * Wih0[g * INS0_ + FDIM_ + j];
    g_xproj[b * G4_ + g] = acc;
}

// ---------------------------------------------------------------------------
// Main recurrence: 64 CTAs (one per batch), 128 threads (2 cells/thread).
// 3 layers fused with a time skew: iter it -> layer0@it, layer1@it-1, layer2@it-2.
// All weights register-resident; only F_proj rows stream from L2 (prefetched).
// ---------------------------------------------------------------------------
__global__ void __launch_bounds__(128, 1) lstm_main(
    const float* __restrict__ Whh0, const float* __restrict__ Whr0,
    const float* __restrict__ Wih1, const float* __restrict__ Whh1,
    const float* __restrict__ bih1, const float* __restrict__ bhh1,
    const float* __restrict__ Whr1,
    const float* __restrict__ Wih2, const float* __restrict__ Whh2,
    const float* __restrict__ bih2, const float* __restrict__ bhh2,
    const float* __restrict__ Whr2,
    float* __restrict__ out) {

    const int b    = blockIdx.x;
    const int tid  = threadIdx.x;
    const int warp = tid >> 5;
    const int lane = tid & 31;

    __shared__ float red[2][4][4];   // [parity][warp][layer], single bar/iter

    // ---- register-resident parameters for this thread's 2 cells ----
    float whh0r[2][4], wih1r[2][4], whh1r[2][4], bb1[2][4];
    float wih2r[2][4], whh2r[2][4], bb2[2][4];
    float xp[2][4], whr0r[2], whr1r[2], whr2r[2];

    #pragma unroll
    for (int c = 0; c < 2; ++c) {
        int j = tid + c * 128;
        #pragma unroll
        for (int g = 0; g < 4; ++g) {
            int gi = g * H_ + j;
            whh0r[c][g] = Whh0[gi];
            wih1r[c][g] = Wih1[gi];
            whh1r[c][g] = Whh1[gi];
            bb1[c][g]   = bih1[gi] + bhh1[gi];
            wih2r[c][g] = Wih2[gi];
            whh2r[c][g] = Whh2[gi];
            bb2[c][g]   = bih2[gi] + bhh2[gi];
            xp[c][g]    = g_xproj[b * G4_ + gi];
        }
        whr0r[c] = Whr0[j];
        whr1r[c] = Whr1[j];
        whr2r[c] = Whr2[j];
    }

    float c0[2] = {0.f, 0.f}, c1[2] = {0.f, 0.f}, c2[2] = {0.f, 0.f};
    float h0 = 0.f, h1 = 0.f, h2 = 0.f;  // h2 kept for symmetry

    // F_proj row prefetch (t=0)
    float fp[2][4], fpn[2][4];
    #pragma unroll
    for (int c = 0; c < 2; ++c)
        #pragma unroll
        for (int g = 0; g < 4; ++g)
            fp[c][g] = g_fproj[(size_t)0 * G4_ + g * H_ + tid + c * 128];

    for (int it = 0; it <= NF_ + 1; ++it) {
        // prefetch next F_proj row (clamped; values unused when out of range)
        {
            int tn = (it + 1 < NF_) ? (it + 1) : (NF_ - 1);
            const float* fr = g_fproj + (size_t)tn * G4_;
            #pragma unroll
            for (int c = 0; c < 2; ++c)
                #pragma unroll
                for (int g = 0; g < 4; ++g)
                    fpn[c][g] = fr[g * H_ + tid + c * 128];
        }

        const bool a0 = (it < NF_);
        const bool a1 = (it >= 1) && (it <= NF_);
        const bool a2 = (it >= 2);

        float p0 = 0.f, p1 = 0.f, p2 = 0.f;

        if (a0) {   // layer 0, timestep it; recurrent scalar h0 (= h0_{it-1})
            #pragma unroll
            for (int c = 0; c < 2; ++c) {
                float gi = fp[c][0] + xp[c][0] + h0 * whh0r[c][0];
                float gf = fp[c][1] + xp[c][1] + h0 * whh0r[c][1];
                float gg = fp[c][2] + xp[c][2] + h0 * whh0r[c][2];
                float go = fp[c][3] + xp[c][3] + h0 * whh0r[c][3];
                float cc = fast_sigmoid(gf) * c0[c] + fast_sigmoid(gi) * fast_tanh(gg);
                c0[c] = cc;
                p0 += fast_sigmoid(go) * fast_tanh(cc) * whr0r[c];
            }
        }
        if (a1) {   // layer 1, timestep it-1; input h0 (= h0_{it-1}), recurrent h1
            #pragma unroll
            for (int c = 0; c < 2; ++c) {
                float gi = bb1[c][0] + h0 * wih1r[c][0] + h1 * whh1r[c][0];
                float gf = bb1[c][1] + h0 * wih1r[c][1] + h1 * whh1r[c][1];
                float gg = bb1[c][2] + h0 * wih1r[c][2] + h1 * whh1r[c][2];
                float go = bb1[c][3] + h0 * wih1r[c][3] + h1 * whh1r[c][3];
                float cc = fast_sigmoid(gf) * c1[c] + fast_sigmoid(gi) * fast_tanh(gg);
                c1[c] = cc;
                p1 += fast_sigmoid(go) * fast_tanh(cc) * whr1r[c];
            }
        }
        if (a2) {   // layer 2, timestep it-2; input h1 (= h1_{it-2}), recurrent h2
            #pragma unroll
            for (int c = 0; c < 2; ++c) {
                float gi = bb2[c][0] + h1 * wih2r[c][0] + h2 * whh2r[c][0];
                float gf = bb2[c][1] + h1 * wih2r[c][1] + h2 * whh2r[c][1];
                float gg = bb2[c][2] + h1 * wih2r[c][2] + h2 * whh2r[c][2];
                float go = bb2[c][3] + h1 * wih2r[c][3] + h2 * whh2r[c][3];
                float cc = fast_sigmoid(gf) * c2[c] + fast_sigmoid(gi) * fast_tanh(gg);
                c2[c] = cc;
                p2 += fast_sigmoid(go) * fast_tanh(cc) * whr2r[c];
            }
        }

        // ---- block reduction of the 3 scalars (interleaved shfl chains) ----
        #pragma unroll
        for (int off = 16; off; off >>= 1) {
            p0 += __shfl_xor_sync(0xffffffffu, p0, off);
            p1 += __shfl_xor_sync(0xffffffffu, p1, off);
            p2 += __shfl_xor_sync(0xffffffffu, p2, off);
        }
        const int buf = it & 1;
        if (lane == 0) {
            red[buf][warp][0] = p0;
            red[buf][warp][1] = p1;
            red[buf][warp][2] = p2;
        }
        __syncthreads();   // single barrier per iteration (double-buffered smem)

        float r0 = red[buf][0][0] + red[buf][1][0] + red[buf][2][0] + red[buf][3][0];
        float r1 = red[buf][0][1] + red[buf][1][1] + red[buf][2][1] + red[buf][3][1];
        float r2 = red[buf][0][2] + red[buf][1][2] + red[buf][2][2] + red[buf][3][2];

        if (a0) h0 = r0;
        if (a1) h1 = r1;
        if (a2) { h2 = r2; out[b * NF_ + (it - 2)] = r2; }

        #pragma unroll
        for (int c = 0; c < 2; ++c)
            #pragma unroll
            for (int g = 0; g < 4; ++g)
                fp[c][g] = fpn[c][g];
    }
}

// ---------------------------------------------------------------------------
// Inputs (metadata order):
// 0 x[64,16]  1 f[1001,128]
// 2 W_ih0[1024,144] 3 W_hh0[1024] 4 b_ih0[1024] 5 b_hh0[1024] 6 W_hr0[256]
// 7 W_ih1[1024]     8 W_hh1      9 b_ih1      10 b_hh1      11 W_hr1
// 12 W_ih2          13 W_hh2     14 b_ih2     15 b_hh2      16 W_hr2
// out: float32 [64, 1001]
// ---------------------------------------------------------------------------
extern "C" void kernel_launch(void* const* d_in, const int* in_sizes, int n_in,
                              void* d_out, int out_size) {
    const float* x     = (const float*)d_in[0];
    const float* f     = (const float*)d_in[1];
    const float* Wih0  = (const float*)d_in[2];
    const float* Whh0  = (const float*)d_in[3];
    const float* bih0  = (const float*)d_in[4];
    const float* bhh0  = (const float*)d_in[5];
    const float* Whr0  = (const float*)d_in[6];
    const float* Wih1  = (const float*)d_in[7];
    const float* Whh1  = (const float*)d_in[8];
    const float* bih1  = (const float*)d_in[9];
    const float* bhh1  = (const float*)d_in[10];
    const float* Whr1  = (const float*)d_in[11];
    const float* Wih2  = (const float*)d_in[12];
    const float* Whh2  = (const float*)d_in[13];
    const float* bih2  = (const float*)d_in[14];
    const float* bhh2  = (const float*)d_in[15];
    const float* Whr2  = (const float*)d_in[16];
    float* out = (float*)d_out;

    fproj_kernel<<<dim3((NF_ + 15) / 16, G4_ / 256), 256>>>(f, Wih0);
    xproj_kernel<<<dim3(B_, G4_ / 256), 256>>>(x, Wih0, bih0, bhh0);
    lstm_main<<<B_, 128>>>(Whh0, Whr0,
                           Wih1, Whh1, bih1, bhh1, Whr1,
                           Wih2, Whh2, bih2, bhh2, Whr2,
                           out);
}

// round 5
// speedup vs baseline: 1.0726x; 1.0726x over previous
#include <cuda_runtime.h>

#define B_     64
#define IN_CH_ 16
#define H_     256
#define FDIM_  128
#define NF_    1001
#define G4_    1024      // 4*H
#define INS0_  144       // FDIM + IN_CH

#define LOG2E_ 1.4426950408889634f

// Scratch (allocation-free: device globals)
__device__ float g_fproj[NF_ * G4_];   // [t][4H]  pre-scaled (-log2e, g-gate -2log2e)
__device__ float g_xproj[B_ * G4_];    // [b][4H]  pre-scaled x-part + layer-0 biases

__device__ __forceinline__ float ex2(float x) {
    float y; asm("ex2.approx.f32 %0, %1;" : "=f"(y) : "f"(x)); return y;
}
__device__ __forceinline__ float frcp(float x) {
    float y; asm("rcp.approx.f32 %0, %1;" : "=f"(y) : "f"(x)); return y;
}

// Gate inputs arrive PRE-SCALED: gi,gf,go = -log2e*raw ; gg = -2log2e*raw.
// sigmoid(i)*tanh(g) = (1-eg) / ((1+ei)(1+eg)),  ei=2^gi, eg=2^gg
// 5 EX2 + 3 RCP per cell (vs 10 MUFU before).
__device__ __forceinline__ float cell_update(float gi, float gf, float gg, float go,
                                             float& c, float whr) {
    float ei = ex2(gi);
    float ef = ex2(gf);
    float eg = ex2(gg);
    float eo = ex2(go);
    float dig = frcp((1.0f + ei) * (1.0f + eg));
    float sf  = frcp(1.0f + ef);
    float cc  = fmaf(sf, c, (1.0f - eg) * dig);
    c = cc;
    float ec  = ex2(cc * (-2.0f * LOG2E_));
    float doc = frcp((1.0f + eo) * (1.0f + ec));
    return (1.0f - ec) * doc * whr;
}

// ---------------------------------------------------------------------------
// Precompute 1: F_proj[t, g] = scale(g) * sum_i f[t,i] * W_ih0[g, i]  (i<128)
// grid (32, 4), block 256: 32 timesteps x 256 gates per block.
// ---------------------------------------------------------------------------
__global__ void fproj_kernel(const float* __restrict__ f,
                             const float* __restrict__ Wih0) {
    __shared__ float fs[32][FDIM_];
    const int tid = threadIdx.x;
    const int t0 = blockIdx.x * 32;

    for (int idx = tid; idx < 32 * FDIM_; idx += 256) {
        int tt = idx >> 7, ii = idx & 127;
        int t = t0 + tt;
        fs[tt][ii] = (t < NF_) ? f[t * FDIM_ + ii] : 0.0f;
    }
    __syncthreads();

    const int g = blockIdx.y * 256 + tid;
    const float scale = (blockIdx.y == 2) ? (-2.0f * LOG2E_) : (-LOG2E_);

    float acc[32];
    #pragma unroll
    for (int tt = 0; tt < 32; ++tt) acc[tt] = 0.0f;

    #pragma unroll 4
    for (int i = 0; i < FDIM_; ++i) {
        float w = Wih0[g * INS0_ + i];
        #pragma unroll
        for (int tt = 0; tt < 32; ++tt) acc[tt] += w * fs[tt][i];
    }
    #pragma unroll
    for (int tt = 0; tt < 32; ++tt) {
        int t = t0 + tt;
        if (t < NF_) g_fproj[(size_t)t * G4_ + g] = acc[tt] * scale;
    }
}

// ---------------------------------------------------------------------------
// Precompute 2: X_proj[b, g] = scale(g) * (b_ih0[g]+b_hh0[g]+sum_j x[b,j]W..)
// ---------------------------------------------------------------------------
__global__ void xproj_kernel(const float* __restrict__ x,
                             const float* __restrict__ Wih0,
                             const float* __restrict__ bih0,
                             const float* __restrict__ bhh0) {
    const int b = blockIdx.x;
    const int g = blockIdx.y * 256 + threadIdx.x;
    const float scale = (blockIdx.y == 2) ? (-2.0f * LOG2E_) : (-LOG2E_);
    float acc = bih0[g] + bhh0[g];
    #pragma unroll
    for (int j = 0; j < IN_CH_; ++j)
        acc += x[b * IN_CH_ + j] * Wih0[g * INS0_ + FDIM_ + j];
    g_xproj[b * G4_ + g] = acc * scale;
}

// ---------------------------------------------------------------------------
// Main recurrence: 64 CTAs (one per batch), 128 threads (2 cells/thread).
// 3 layers fused with time skew (layer l at iter it computes timestep it-l).
// Peeled prologue/epilogue -> branch-free steady loop.
// Interleaved 3-chain shfl butterfly + 1 barrier + LDS.128 partial combine.
// ---------------------------------------------------------------------------
__global__ void __launch_bounds__(128, 1) lstm_main(
    const float* __restrict__ Whh0, const float* __restrict__ Whr0,
    const float* __restrict__ Wih1, const float* __restrict__ Whh1,
    const float* __restrict__ bih1, const float* __restrict__ bhh1,
    const float* __restrict__ Whr1,
    const float* __restrict__ Wih2, const float* __restrict__ Whh2,
    const float* __restrict__ bih2, const float* __restrict__ bhh2,
    const float* __restrict__ Whr2,
    float* __restrict__ out) {

    const int b    = blockIdx.x;
    const int tid  = threadIdx.x;
    const int warp = tid >> 5;
    const int lane = tid & 31;

    __shared__ __align__(16) float red[2][3][4];   // [parity][layer][warp]

    const float gsc[4] = { -LOG2E_, -LOG2E_, -2.0f * LOG2E_, -LOG2E_ };

    // ---- register-resident, pre-scaled parameters (2 cells/thread) ----
    float whh0r[2][4], wih1r[2][4], whh1r[2][4], bb1[2][4];
    float wih2r[2][4], whh2r[2][4], bb2[2][4];
    float xp[2][4], whr0r[2], whr1r[2], whr2r[2];

    #pragma unroll
    for (int c = 0; c < 2; ++c) {
        int j = tid + c * 128;
        #pragma unroll
        for (int g = 0; g < 4; ++g) {
            int gi = g * H_ + j;
            float s = gsc[g];
            whh0r[c][g] = Whh0[gi] * s;
            wih1r[c][g] = Wih1[gi] * s;
            whh1r[c][g] = Whh1[gi] * s;
            bb1[c][g]   = (bih1[gi] + bhh1[gi]) * s;
            wih2r[c][g] = Wih2[gi] * s;
            whh2r[c][g] = Whh2[gi] * s;
            bb2[c][g]   = (bih2[gi] + bhh2[gi]) * s;
            xp[c][g]    = g_xproj[b * G4_ + gi];     // already scaled
        }
        whr0r[c] = Whr0[j];
        whr1r[c] = Whr1[j];
        whr2r[c] = Whr2[j];
    }

    float c0[2] = {0.f, 0.f}, c1[2] = {0.f, 0.f}, c2[2] = {0.f, 0.f};
    float h0 = 0.f, h1 = 0.f, h2 = 0.f;

    float fp[2][4], fpn[2][4];
    #pragma unroll
    for (int c = 0; c < 2; ++c)
        #pragma unroll
        for (int g = 0; g < 4; ++g)
            fp[c][g] = g_fproj[(size_t)0 * G4_ + g * H_ + tid + c * 128];

#define DO_STEP(A0, A1, A2, IT)                                               \
{                                                                             \
    const int it_ = (IT);                                                     \
    if (A0) {                                                                 \
        int tn = it_ + 1; if (tn > NF_ - 1) tn = NF_ - 1;                     \
        const float* fr = g_fproj + (size_t)tn * G4_;                         \
        _Pragma("unroll")                                                     \
        for (int c_ = 0; c_ < 2; ++c_)                                        \
            _Pragma("unroll")                                                 \
            for (int g_ = 0; g_ < 4; ++g_)                                    \
                fpn[c_][g_] = fr[g_ * H_ + tid + c_ * 128];                   \
    }                                                                         \
    float p0 = 0.f, p1 = 0.f, p2 = 0.f;                                       \
    if (A0) {                                                                 \
        _Pragma("unroll")                                                     \
        for (int c_ = 0; c_ < 2; ++c_) {                                      \
            float gi = (fp[c_][0] + xp[c_][0]) + h0 * whh0r[c_][0];           \
            float gf = (fp[c_][1] + xp[c_][1]) + h0 * whh0r[c_][1];           \
            float gg = (fp[c_][2] + xp[c_][2]) + h0 * whh0r[c_][2];           \
            float go = (fp[c_][3] + xp[c_][3]) + h0 * whh0r[c_][3];           \
            p0 += cell_update(gi, gf, gg, go, c0[c_], whr0r[c_]);             \
        }                                                                     \
    }                                                                         \
    if (A1) {                                                                 \
        _Pragma("unroll")                                                     \
        for (int c_ = 0; c_ < 2; ++c_) {                                      \
            float gi = bb1[c_][0] + h0 * wih1r[c_][0] + h1 * whh1r[c_][0];    \
            float gf = bb1[c_][1] + h0 * wih1r[c_][1] + h1 * whh1r[c_][1];    \
            float gg = bb1[c_][2] + h0 * wih1r[c_][2] + h1 * whh1r[c_][2];    \
            float go = bb1[c_][3] + h0 * wih1r[c_][3] + h1 * whh1r[c_][3];    \
            p1 += cell_update(gi, gf, gg, go, c1[c_], whr1r[c_]);             \
        }                                                                     \
    }                                                                         \
    if (A2) {                                                                 \
        _Pragma("unroll")                                                     \
        for (int c_ = 0; c_ < 2; ++c_) {                                      \
            float gi = bb2[c_][0] + h1 * wih2r[c_][0] + h2 * whh2r[c_][0];    \
            float gf = bb2[c_][1] + h1 * wih2r[c_][1] + h2 * whh2r[c_][1];    \
            float gg = bb2[c_][2] + h1 * wih2r[c_][2] + h2 * whh2r[c_][2];    \
            float go = bb2[c_][3] + h1 * wih2r[c_][3] + h2 * whh2r[c_][3];    \
            p2 += cell_update(gi, gf, gg, go, c2[c_], whr2r[c_]);             \
        }                                                                     \
    }                                                                         \
    _Pragma("unroll")                                                         \
    for (int off_ = 16; off_; off_ >>= 1) {                                   \
        p0 += __shfl_xor_sync(0xffffffffu, p0, off_);                         \
        p1 += __shfl_xor_sync(0xffffffffu, p1, off_);                         \
        p2 += __shfl_xor_sync(0xffffffffu, p2, off_);                         \
    }                                                                         \
    const int buf_ = it_ & 1;                                                 \
    if (lane == 0) {                                                          \
        red[buf_][0][warp] = p0;                                              \
        red[buf_][1][warp] = p1;                                              \
        red[buf_][2][warp] = p2;                                              \
    }                                                                         \
    __syncthreads();                                                          \
    if (A0) {                                                                 \
        float4 q = *(const float4*)&red[buf_][0][0];                          \
        h0 = (q.x + q.y) + (q.z + q.w);                                       \
    }                                                                         \
    if (A1) {                                                                 \
        float4 q = *(const float4*)&red[buf_][1][0];                          \
        h1 = (q.x + q.y) + (q.z + q.w);                                       \
    }                                                                         \
    if (A2) {                                                                 \
        float4 q = *(const float4*)&red[buf_][2][0];                          \
        float r2 = (q.x + q.y) + (q.z + q.w);                                 \
        h2 = r2;                                                              \
        out[b * NF_ + (it_ - 2)] = r2;                                        \
    }                                                                         \
    if (A0) {                                                                 \
        _Pragma("unroll")                                                     \
        for (int c_ = 0; c_ < 2; ++c_)                                        \
            _Pragma("unroll")                                                 \
            for (int g_ = 0; g_ < 4; ++g_)                                    \
                fp[c_][g_] = fpn[c_][g_];                                     \
    }                                                                         \
}

    // prologue
    DO_STEP(true,  false, false, 0)
    DO_STEP(true,  true,  false, 1)
    // steady state: branch-free
    for (int it = 2; it < NF_; ++it) {
        DO_STEP(true, true, true, it)
    }
    // epilogue
    DO_STEP(false, true,  true, NF_)
    DO_STEP(false, false, true, NF_ + 1)

#undef DO_STEP
}

// ---------------------------------------------------------------------------
// Inputs (metadata order):
// 0 x[64,16]  1 f[1001,128]
// 2 W_ih0[1024,144] 3 W_hh0[1024] 4 b_ih0[1024] 5 b_hh0[1024] 6 W_hr0[256]
// 7..11 layer1, 12..16 layer2.  out: float32 [64,1001]
// ---------------------------------------------------------------------------
extern "C" void kernel_launch(void* const* d_in, const int* in_sizes, int n_in,
                              void* d_out, int out_size) {
    const float* x     = (const float*)d_in[0];
    const float* f     = (const float*)d_in[1];
    const float* Wih0  = (const float*)d_in[2];
    const float* Whh0  = (const float*)d_in[3];
    const float* bih0  = (const float*)d_in[4];
    const float* bhh0  = (const float*)d_in[5];
    const float* Whr0  = (const float*)d_in[6];
    const float* Wih1  = (const float*)d_in[7];
    const float* Whh1  = (const float*)d_in[8];
    const float* bih1  = (const float*)d_in[9];
    const float* bhh1  = (const float*)d_in[10];
    const float* Whr1  = (const float*)d_in[11];
    const float* Wih2  = (const float*)d_in[12];
    const float* Whh2  = (const float*)d_in[13];
    const float* bih2  = (const float*)d_in[14];
    const float* bhh2  = (const float*)d_in[15];
    const float* Whr2  = (const float*)d_in[16];
    float* out = (float*)d_out;

    fproj_kernel<<<dim3((NF_ + 31) / 32, G4_ / 256), 256>>>(f, Wih0);
    xproj_kernel<<<dim3(B_, G4_ / 256), 256>>>(x, Wih0, bih0, bhh0);
    lstm_main<<<B_, 128>>>(Whh0, Whr0,
                           Wih1, Whh1, bih1, bhh1, Whr1,
                           Wih2, Whh2, bih2, bhh2, Whr2,
                           out);
}

// round 8
// speedup vs baseline: 1.0944x; 1.0203x over previous
#include <cuda_runtime.h>

#define B_     64
#define IN_CH_ 16
#define H_     256
#define FDIM_  128
#define NF_    1001
#define G4_    1024      // 4*H
#define INS0_  144       // FDIM + IN_CH

#define LOG2E_ 1.4426950408889634f
#define ECLAMP_ 30.0f    // clamp scaled exponent args: 2^30 each, product <= 2^120 < inf

// Scratch (allocation-free: device globals)
__device__ float g_fproj[NF_ * G4_];   // [t][4H]  pre-scaled (-log2e, g-gate -2log2e)
__device__ float g_xproj[B_ * G4_];    // [b][4H]  pre-scaled x-part + layer-0 biases

__device__ __forceinline__ float ex2(float x) {
    float y; asm("ex2.approx.f32 %0, %1;" : "=f"(y) : "f"(x)); return y;
}
__device__ __forceinline__ float frcp(float x) {
    float y; asm("rcp.approx.f32 %0, %1;" : "=f"(y) : "f"(x)); return y;
}

// Gate inputs PRE-SCALED: gi,gf,gg,go = -log2e*raw (gg: -2log2e*raw), i/f/g CLAMPED <= 30.
// One rcp covers sigmoid(i)*tanh(g) AND sigmoid(f):
//   r3 = 1/((1+ei)(1+eg)(1+ef));  dig = (1+ef)*r3;  sf = (1+ei)(1+eg)*r3
// 5 EX2 + 2 RCP per cell.
__device__ __forceinline__ float cell_update(float gi, float gf, float gg, float go,
                                             float& c, float whr) {
    float ei = ex2(gi);
    float ef = ex2(gf);
    float eg = ex2(gg);
    float eo = ex2(go);
    float pig = (1.0f + ei) * (1.0f + eg);
    float pf  = 1.0f + ef;
    float r3  = frcp(pig * pf);
    float dig = pf  * r3;     // 1/((1+ei)(1+eg))
    float sf  = pig * r3;     // 1/(1+ef)
    float cc  = fmaf(sf, c, (1.0f - eg) * dig);
    c = cc;
    float ec  = ex2(cc * (-2.0f * LOG2E_));
    float doc = frcp((1.0f + eo) * (1.0f + ec));
    return (1.0f - ec) * doc * whr;
}

// ---------------------------------------------------------------------------
// Precompute 1: F_proj[t, g] = scale(g) * sum_i f[t,i] * W_ih0[g, i]  (i<128)
// grid (32, 4), block 256. float4-vectorized smem tile [tt][i/4].
// ---------------------------------------------------------------------------
__global__ void fproj_kernel(const float* __restrict__ f,
                             const float* __restrict__ Wih0) {
    __shared__ float4 fs4[32][FDIM_ / 4];   // [tt][i4]
    const int tid = threadIdx.x;
    const int t0 = blockIdx.x * 32;

    const float4* f4 = (const float4*)f;
    for (int idx = tid; idx < 32 * (FDIM_ / 4); idx += 256) {
        int tt = idx >> 5, i4 = idx & 31;
        int t = t0 + tt;
        fs4[tt][i4] = (t < NF_) ? f4[t * (FDIM_ / 4) + i4]
                                : make_float4(0.f, 0.f, 0.f, 0.f);
    }
    __syncthreads();

    const int g = blockIdx.y * 256 + tid;
    const float scale = (blockIdx.y == 2) ? (-2.0f * LOG2E_) : (-LOG2E_);

    float acc[32];
    #pragma unroll
    for (int tt = 0; tt < 32; ++tt) acc[tt] = 0.0f;

    const float* wrow = Wih0 + (size_t)g * INS0_;   // 576B rows -> 16B aligned
    #pragma unroll 4
    for (int i4 = 0; i4 < FDIM_ / 4; ++i4) {
        float4 w = ((const float4*)wrow)[i4];       // LDG.128
        #pragma unroll
        for (int tt = 0; tt < 32; ++tt) {
            float4 fv = fs4[tt][i4];                // LDS.128 broadcast
            acc[tt] += w.x * fv.x + w.y * fv.y + w.z * fv.z + w.w * fv.w;
        }
    }
    #pragma unroll
    for (int tt = 0; tt < 32; ++tt) {
        int t = t0 + tt;
        if (t < NF_) g_fproj[(size_t)t * G4_ + g] = acc[tt] * scale;
    }
}

// ---------------------------------------------------------------------------
// Precompute 2: X_proj[b, g] = scale(g) * (b_ih0[g]+b_hh0[g]+sum_j x[b,j]W..)
// ---------------------------------------------------------------------------
__global__ void xproj_kernel(const float* __restrict__ x,
                             const float* __restrict__ Wih0,
                             const float* __restrict__ bih0,
                             const float* __restrict__ bhh0) {
    const int b = blockIdx.x;
    const int g = blockIdx.y * 256 + threadIdx.x;
    const float scale = (blockIdx.y == 2) ? (-2.0f * LOG2E_) : (-LOG2E_);
    float acc = bih0[g] + bhh0[g];
    #pragma unroll
    for (int j = 0; j < IN_CH_; ++j)
        acc += x[b * IN_CH_ + j] * Wih0[g * INS0_ + FDIM_ + j];
    g_xproj[b * G4_ + g] = acc * scale;
}

// ---------------------------------------------------------------------------
// Main recurrence: 64 CTAs, 256 threads (8 warps -> 2 per SMSP for latency
// hiding), 1 cell/thread/layer. 3 layers time-skewed. Peeled boundaries.
// Per-warp shfl butterfly + 1 bar/iter + 8-partial smem combine.
// ---------------------------------------------------------------------------
__global__ void __launch_bounds__(256, 1) lstm_main(
    const float* __restrict__ Whh0, const float* __restrict__ Whr0,
    const float* __restrict__ Wih1, const float* __restrict__ Whh1,
    const float* __restrict__ bih1, const float* __restrict__ bhh1,
    const float* __restrict__ Whr1,
    const float* __restrict__ Wih2, const float* __restrict__ Whh2,
    const float* __restrict__ bih2, const float* __restrict__ bhh2,
    const float* __restrict__ Whr2,
    float* __restrict__ out) {

    const int b    = blockIdx.x;
    const int tid  = threadIdx.x;
    const int warp = tid >> 5;
    const int lane = tid & 31;

    __shared__ __align__(16) float red[2][3][8];   // [parity][layer][warp]

    const float gsc[4] = { -LOG2E_, -LOG2E_, -2.0f * LOG2E_, -LOG2E_ };

    // ---- register-resident, pre-scaled parameters (1 cell/thread/layer) ----
    float whh0r[4], wih1r[4], whh1r[4], bb1[4];
    float wih2r[4], whh2r[4], bb2[4];
    float xp[4], whr0r, whr1r, whr2r;

    #pragma unroll
    for (int g = 0; g < 4; ++g) {
        int gi = g * H_ + tid;
        float s = gsc[g];
        whh0r[g] = Whh0[gi] * s;
        wih1r[g] = Wih1[gi] * s;
        whh1r[g] = Whh1[gi] * s;
        bb1[g]   = (bih1[gi] + bhh1[gi]) * s;
        wih2r[g] = Wih2[gi] * s;
        whh2r[g] = Whh2[gi] * s;
        bb2[g]   = (bih2[gi] + bhh2[gi]) * s;
        xp[g]    = g_xproj[b * G4_ + gi];     // already scaled
    }
    whr0r = Whr0[tid];
    whr1r = Whr1[tid];
    whr2r = Whr2[tid];

    float c0 = 0.f, c1 = 0.f, c2 = 0.f;
    float h0 = 0.f, h1 = 0.f, h2 = 0.f;

    float fp[4], fpn[4];
    #pragma unroll
    for (int g = 0; g < 4; ++g)
        fp[g] = g_fproj[(size_t)0 * G4_ + g * H_ + tid];

#define DO_STEP(A0, A1, A2, IT)                                               \
{                                                                             \
    const int it_ = (IT);                                                     \
    if (A0) {                                                                 \
        int tn = it_ + 1; if (tn > NF_ - 1) tn = NF_ - 1;                     \
        const float* fr = g_fproj + (size_t)tn * G4_;                         \
        _Pragma("unroll")                                                     \
        for (int g_ = 0; g_ < 4; ++g_)                                        \
            fpn[g_] = fr[g_ * H_ + tid];                                      \
    }                                                                         \
    float p0 = 0.f, p1 = 0.f, p2 = 0.f;                                       \
    if (A0) {                                                                 \
        float gi = fminf((fp[0] + xp[0]) + h0 * whh0r[0], ECLAMP_);           \
        float gf = fminf((fp[1] + xp[1]) + h0 * whh0r[1], ECLAMP_);           \
        float gg = fminf((fp[2] + xp[2]) + h0 * whh0r[2], ECLAMP_);           \
        float go = (fp[3] + xp[3]) + h0 * whh0r[3];                           \
        p0 = cell_update(gi, gf, gg, go, c0, whr0r);                          \
    }                                                                         \
    if (A1) {                                                                 \
        float gi = fminf(bb1[0] + h0 * wih1r[0] + h1 * whh1r[0], ECLAMP_);    \
        float gf = fminf(bb1[1] + h0 * wih1r[1] + h1 * whh1r[1], ECLAMP_);    \
        float gg = fminf(bb1[2] + h0 * wih1r[2] + h1 * whh1r[2], ECLAMP_);    \
        float go = bb1[3] + h0 * wih1r[3] + h1 * whh1r[3];                    \
        p1 = cell_update(gi, gf, gg, go, c1, whr1r);                          \
    }                                                                         \
    if (A2) {                                                                 \
        float gi = fminf(bb2[0] + h1 * wih2r[0] + h2 * whh2r[0], ECLAMP_);    \
        float gf = fminf(bb2[1] + h1 * wih2r[1] + h2 * whh2r[1], ECLAMP_);    \
        float gg = fminf(bb2[2] + h1 * wih2r[2] + h2 * whh2r[2], ECLAMP_);    \
        float go = bb2[3] + h1 * wih2r[3] + h2 * whh2r[3];                    \
        p2 = cell_update(gi, gf, gg, go, c2, whr2r);                          \
    }                                                                         \
    _Pragma("unroll")                                                         \
    for (int off_ = 16; off_; off_ >>= 1) {                                   \
        p0 += __shfl_xor_sync(0xffffffffu, p0, off_);                         \
        p1 += __shfl_xor_sync(0xffffffffu, p1, off_);                         \
        p2 += __shfl_xor_sync(0xffffffffu, p2, off_);                         \
    }                                                                         \
    const int buf_ = it_ & 1;                                                 \
    if (lane == 0) {                                                          \
        red[buf_][0][warp] = p0;                                              \
        red[buf_][1][warp] = p1;                                              \
        red[buf_][2][warp] = p2;                                              \
    }                                                                         \
    __syncthreads();                                                          \
    if (A0) {                                                                 \
        float4 qa = *(const float4*)&red[buf_][0][0];                         \
        float4 qb = *(const float4*)&red[buf_][0][4];                         \
        h0 = ((qa.x + qa.y) + (qa.z + qa.w)) + ((qb.x + qb.y) + (qb.z + qb.w)); \
    }                                                                         \
    if (A1) {                                                                 \
        float4 qa = *(const float4*)&red[buf_][1][0];                         \
        float4 qb = *(const float4*)&red[buf_][1][4];                         \
        h1 = ((qa.x + qa.y) + (qa.z + qa.w)) + ((qb.x + qb.y) + (qb.z + qb.w)); \
    }                                                                         \
    if (A2) {                                                                 \
        float4 qa = *(const float4*)&red[buf_][2][0];                         \
        float4 qb = *(const float4*)&red[buf_][2][4];                         \
        float r2 = ((qa.x + qa.y) + (qa.z + qa.w)) + ((qb.x + qb.y) + (qb.z + qb.w)); \
        h2 = r2;                                                              \
        if (tid == 0) out[b * NF_ + (it_ - 2)] = r2;                          \
    }                                                                         \
    if (A0) {                                                                 \
        _Pragma("unroll")                                                     \
        for (int g_ = 0; g_ < 4; ++g_)                                        \
            fp[g_] = fpn[g_];                                                 \
    }                                                                         \
}

    // prologue
    DO_STEP(true,  false, false, 0)
    DO_STEP(true,  true,  false, 1)
    // steady state: branch-free
    for (int it = 2; it < NF_; ++it) {
        DO_STEP(true, true, true, it)
    }
    // epilogue
    DO_STEP(false, true,  true, NF_)
    DO_STEP(false, false, true, NF_ + 1)

#undef DO_STEP
}

// ---------------------------------------------------------------------------
// Inputs (metadata order):
// 0 x[64,16]  1 f[1001,128]
// 2 W_ih0[1024,144] 3 W_hh0[1024] 4 b_ih0[1024] 5 b_hh0[1024] 6 W_hr0[256]
// 7..11 layer1, 12..16 layer2.  out: float32 [64,1001]
// ---------------------------------------------------------------------------
extern "C" void kernel_launch(void* const* d_in, const int* in_sizes, int n_in,
                              void* d_out, int out_size) {
    const float* x     = (const float*)d_in[0];
    const float* f     = (const float*)d_in[1];
    const float* Wih0  = (const float*)d_in[2];
    const float* Whh0  = (const float*)d_in[3];
    const float* bih0  = (const float*)d_in[4];
    const float* bhh0  = (const float*)d_in[5];
    const float* Whr0  = (const float*)d_in[6];
    const float* Wih1  = (const float*)d_in[7];
    const float* Whh1  = (const float*)d_in[8];
    const float* bih1  = (const float*)d_in[9];
    const float* bhh1  = (const float*)d_in[10];
    const float* Whr1  = (const float*)d_in[11];
    const float* Wih2  = (const float*)d_in[12];
    const float* Whh2  = (const float*)d_in[13];
    const float* bih2  = (const float*)d_in[14];
    const float* bhh2  = (const float*)d_in[15];
    const float* Whr2  = (const float*)d_in[16];
    float* out = (float*)d_out;

    fproj_kernel<<<dim3((NF_ + 31) / 32, G4_ / 256), 256>>>(f, Wih0);
    xproj_kernel<<<dim3(B_, G4_ / 256), 256>>>(x, Wih0, bih0, bhh0);
    lstm_main<<<B_, 256>>>(Whh0, Whr0,
                           Wih1, Whh1, bih1, bhh1, Whr1,
                           Wih2, Whh2, bih2, bhh2, Whr2,
                           out);
}